// round 12
// baseline (speedup 1.0000x reference)
#include <cuda_runtime.h>
#include <cuda_fp16.h>
#include <math.h>
#include <stdint.h>

// ---------------------------------------------------------------------------
// Problem constants
// ---------------------------------------------------------------------------
#define B_   4
#define T_   2048
#define D_   1024
#define H_   16
#define G_   4
#define HD_  64
#define BT_  (B_ * T_)          // 8192
#define QKVW 1536                // fused Q|K|V projection width

// ---------------------------------------------------------------------------
// Scratch (device globals -- no allocation allowed)
// ---------------------------------------------------------------------------
__device__ float g_qkv[BT_ * QKVW];       // fused q|k|v projection fp32
__device__ float2 g_cs[T_ * 32];

__device__ __half g_x16[BT_ * D_];
__device__ __half g_wqkv16[QKVW * D_];    // Wq | Wk | Wv rows
__device__ __half g_wo16[D_ * D_];
__device__ __half g_q16[BT_ * D_];
__device__ __half g_k16[BT_ * G_ * HD_];
__device__ __half g_vt16[B_ * G_ * HD_ * T_];
__device__ __half g_o16[BT_ * D_];

// ---------------------------------------------------------------------------
// PTX helpers (base sm_100-legal)
// ---------------------------------------------------------------------------
__device__ __forceinline__ uint32_t smem_u32(const void* p) {
    uint32_t a;
    asm("{ .reg .u64 t; cvta.to.shared.u64 t, %1; cvt.u32.u64 %0, t; }"
        : "=r"(a) : "l"(p));
    return a;
}
__device__ __forceinline__ void ldsm_x4(uint32_t (&r)[4], uint32_t addr) {
    asm volatile("ldmatrix.sync.aligned.m8n8.x4.shared.b16 {%0,%1,%2,%3}, [%4];"
                 : "=r"(r[0]), "=r"(r[1]), "=r"(r[2]), "=r"(r[3]) : "r"(addr));
}
__device__ __forceinline__ void mma_f16(float (&d)[4], const uint32_t (&a)[4],
                                        uint32_t b0, uint32_t b1) {
    asm volatile(
        "mma.sync.aligned.m16n8k16.row.col.f32.f16.f16.f32 "
        "{%0,%1,%2,%3}, {%4,%5,%6,%7}, {%8,%9}, {%0,%1,%2,%3};"
        : "+f"(d[0]), "+f"(d[1]), "+f"(d[2]), "+f"(d[3])
        : "r"(a[0]), "r"(a[1]), "r"(a[2]), "r"(a[3]), "r"(b0), "r"(b1));
}
__device__ __forceinline__ float ex2(float x) {
    float y;
    asm("ex2.approx.ftz.f32 %0, %1;" : "=f"(y) : "f"(x));
    return y;
}
__device__ __forceinline__ uint32_t pack_h2(float x, float y) {
    __half2 h = __floats2half2_rn(x, y);
    return *(uint32_t*)&h;
}
#define STS128(addr, v) \
    asm volatile("st.shared.v4.b32 [%0], {%1,%2,%3,%4};" \
                 :: "r"(addr), "r"((v).x), "r"((v).y), "r"((v).z), "r"((v).w))
#define CP_ASYNC16(dst, src) \
    asm volatile("cp.async.cg.shared.global [%0], [%1], 16;" \
                 :: "r"(dst), "l"(src))
#define CP_COMMIT() asm volatile("cp.async.commit_group;" ::: "memory")
#define CP_WAIT1()  asm volatile("cp.async.wait_group 1;" ::: "memory")
#define CP_WAIT0()  asm volatile("cp.async.wait_group 0;" ::: "memory")

// ---------------------------------------------------------------------------
// Fused prologue: x->fp16, Wq|Wk|Wv|Wo->fp16, rope table. One launch.
// ---------------------------------------------------------------------------
#define NB_X   8192
#define NB_WQ  1024
#define NB_WK  256
#define NB_WV  256
#define NB_WO  1024
#define NB_CS  256
#define NB_TOT (NB_X + NB_WQ + NB_WK + NB_WV + NB_WO + NB_CS)

__global__ void __launch_bounds__(256)
prep(const float* __restrict__ x,  const float* __restrict__ Wq,
     const float* __restrict__ Wk, const float* __restrict__ Wv,
     const float* __restrict__ Wo,
     __half* __restrict__ x16, __half* __restrict__ wqkv16,
     __half* __restrict__ wo16, float2* __restrict__ cs)
{
    const int bid = blockIdx.x;
    const int tid = threadIdx.x;

    const float* src; __half* dst; int i;
    if (bid < NB_X) {
        i = bid * 256 + tid; src = x; dst = x16;
    } else if (bid < NB_X + NB_WQ) {
        i = (bid - NB_X) * 256 + tid; src = Wq; dst = wqkv16;
    } else if (bid < NB_X + NB_WQ + NB_WK) {
        i = (bid - NB_X - NB_WQ) * 256 + tid;
        src = Wk; dst = wqkv16 + (size_t)D_ * D_;
    } else if (bid < NB_X + NB_WQ + NB_WK + NB_WV) {
        i = (bid - NB_X - NB_WQ - NB_WK) * 256 + tid;
        src = Wv; dst = wqkv16 + (size_t)(D_ + 256) * D_;
    } else if (bid < NB_X + NB_WQ + NB_WK + NB_WV + NB_WO) {
        i = (bid - NB_X - NB_WQ - NB_WK - NB_WV) * 256 + tid;
        src = Wo; dst = wo16;
    } else {
        const int idx = (bid - (NB_TOT - NB_CS)) * 256 + tid;
        const int t = idx >> 5, l = idx & 31;
        double inv_freq = pow(10000.0, -(double)l / 32.0);
        double ang = (double)t * inv_freq;
        cs[idx] = make_float2((float)cos(ang), (float)sin(ang));
        return;
    }
    float4 v = ((const float4*)src)[i];
    uint2 o = {pack_h2(v.x, v.y), pack_h2(v.z, v.w)};
    ((uint2*)dst)[i] = o;
}

// ---------------------------------------------------------------------------
// Tensor-core GEMM (HMMA fp16): C[M,N] = A16[M,K] @ B16[N,K]^T.
// CTA 128x128, 8 warps, warp tile 64x32, KC=32, 3-stage cp.async, 2 CTAs/SM.
// ---------------------------------------------------------------------------
#define KC      32
#define LDT     40
#define ATILEB  (128 * LDT * 2)
#define BTILEB  (128 * LDT * 2)
#define STAGEB  (ATILEB + BTILEB)
#define GEMM_SMEM (3 * STAGEB)            // 61440 B

__global__ void __launch_bounds__(256, 2)
gemm_h1(const __half* __restrict__ A16, const __half* __restrict__ B16,
        float* __restrict__ C, int M, int N, int K)
{
    extern __shared__ char smraw[];
    const uint32_t sb = smem_u32(smraw);

    const int tid  = threadIdx.x;
    const int lane = tid & 31;
    const int wid  = tid >> 5;
    const int wm   = wid & 1;
    const int wn   = wid >> 1;
    const int m0 = blockIdx.y * 128;
    const int n0 = blockIdx.x * 128;

    const int r0   = tid >> 2;
    const int cseg = (tid & 3) * 8;
    const __half* pA = A16 + (size_t)(m0 + r0) * K + cseg;
    const __half* pB = B16 + (size_t)(n0 + r0) * K + cseg;
    const uint32_t dA = (uint32_t)(r0 * LDT + cseg) * 2;
    const size_t rstep = (size_t)64 * K;
    const uint32_t dstep = 64 * LDT * 2;

    const uint32_t a_off = (uint32_t)(((wm * 64 + (lane & 15)) * LDT
                                       + (lane >> 4) * 8) * 2);
    const uint32_t b4_off = (uint32_t)(((wn * 32 + (lane & 7)
                                         + ((lane >> 4) & 1) * 8) * LDT) * 2
                                       + ((lane >> 3) & 1) * 16);

    float acc[4][4][4];
#pragma unroll
    for (int i = 0; i < 4; i++)
#pragma unroll
        for (int j = 0; j < 4; j++)
#pragma unroll
            for (int e = 0; e < 4; e++) acc[i][j][e] = 0.f;

    const int nch = K / KC;

#define ISSUE(c) do {                                                       \
        const uint32_t st_ = sb + ((c) % 3) * STAGEB;                       \
        const size_t k0_ = (size_t)(c) * KC;                                \
        CP_ASYNC16(st_ + dA,                    pA + k0_);                  \
        CP_ASYNC16(st_ + dA + dstep,            pA + k0_ + rstep);          \
        CP_ASYNC16(st_ + ATILEB + dA,           pB + k0_);                  \
        CP_ASYNC16(st_ + ATILEB + dA + dstep,   pB + k0_ + rstep);          \
        CP_COMMIT();                                                        \
    } while (0)

    ISSUE(0);
    ISSUE(1);

    for (int c = 0; c < nch; c++) {
        if (c + 2 < nch) CP_WAIT1(); else CP_WAIT0();
        __syncthreads();
        if (c + 2 < nch) ISSUE(c + 2);

        const uint32_t tb = sb + (c % 3) * STAGEB;
        const uint32_t aT = tb;
        const uint32_t bT = tb + ATILEB;

#pragma unroll
        for (int ks = 0; ks < 2; ks++) {
            const uint32_t ksb = ks * 32;
            uint32_t af[4][4];
#pragma unroll
            for (int mt = 0; mt < 4; mt++)
                ldsm_x4(af[mt], aT + a_off + mt * (16 * LDT * 2) + ksb);
#pragma unroll
            for (int ntp = 0; ntp < 2; ntp++) {
                uint32_t bh[4];
                ldsm_x4(bh, bT + b4_off + ntp * (16 * LDT * 2) + ksb);
#pragma unroll
                for (int mt = 0; mt < 4; mt++) {
                    mma_f16(acc[mt][2 * ntp],     af[mt], bh[0], bh[1]);
                    mma_f16(acc[mt][2 * ntp + 1], af[mt], bh[2], bh[3]);
                }
            }
        }
    }
#undef ISSUE

#pragma unroll
    for (int mt = 0; mt < 4; mt++) {
        const int r = m0 + wm * 64 + mt * 16 + (lane >> 2);
#pragma unroll
        for (int nt = 0; nt < 4; nt++) {
            const int cc = n0 + wn * 32 + nt * 8 + (lane & 3) * 2;
            float2 v0 = {acc[mt][nt][0], acc[mt][nt][1]};
            float2 v1 = {acc[mt][nt][2], acc[mt][nt][3]};
            *(float2*)&C[(size_t)r * N + cc]       = v0;
            *(float2*)&C[(size_t)(r + 8) * N + cc] = v1;
        }
    }
}

// ---------------------------------------------------------------------------
// Fused RMSNorm + RoPE for q AND k (block-range split), fp32 in -> fp16 out.
// q: blocks [0, BT_*H_/8); k: blocks [BT_*H_/8, +BT_*G_/8)
// ---------------------------------------------------------------------------
#define NB_RQ (BT_ * H_ / 8)   // 16384
#define NB_RK (BT_ * G_ / 8)   // 4096

__global__ void __launch_bounds__(256)
rmsrope_qk(const float* __restrict__ qkv,
           const float* __restrict__ qn_w, const float* __restrict__ kn_w,
           __half* __restrict__ q16, __half* __restrict__ k16,
           const float2* __restrict__ cs)
{
    const int lane   = threadIdx.x & 31;
    const int warpid = threadIdx.x >> 5;

    const float* p;
    const float* w;
    __half* outp;
    int t;
    if (blockIdx.x < NB_RQ) {
        const int row  = blockIdx.x * 8 + warpid;      // bt*16 + head
        const int bt   = row >> 4;
        const int head = row & 15;
        t = bt & (T_ - 1);
        p = qkv + (size_t)bt * QKVW + head * HD_;
        w = qn_w;
        outp = q16 + (size_t)bt * D_ + head * HD_;
    } else {
        const int row = (blockIdx.x - NB_RQ) * 8 + warpid;   // bt*4 + g
        const int bt  = row >> 2;
        const int g   = row & 3;
        t = bt & (T_ - 1);
        p = qkv + (size_t)bt * QKVW + D_ + g * HD_;
        w = kn_w;
        outp = k16 + (size_t)bt * (G_ * HD_) + g * HD_;
    }

    float2 x = *(const float2*)&p[2 * lane];
    float ss = x.x * x.x + x.y * x.y;
#pragma unroll
    for (int o = 16; o > 0; o >>= 1)
        ss += __shfl_xor_sync(0xffffffffu, ss, o);

    float rms = rsqrtf(ss * (1.0f / HD_) + 1e-6f);
    float xn1 = x.x * rms * w[2 * lane];
    float xn2 = x.y * rms * w[2 * lane + 1];

    float2 csv = cs[t * 32 + lane];
    float ox = xn1 * csv.x - xn2 * csv.y;
    float oy = xn2 * csv.x + xn1 * csv.y;

    *(uint32_t*)&outp[2 * lane] = pack_h2(ox, oy);
}

// ---------------------------------------------------------------------------
// V convert + transpose: fp32 strided [bt, 1536] +1280 -> fp16 [b,g,hd,T]
// ---------------------------------------------------------------------------
__global__ void __launch_bounds__(256)
vconv(const float* __restrict__ v, int rowstride, __half* __restrict__ vt)
{
    __shared__ float s[64][65];
    const int t0 = blockIdx.x * 64;
    const int g  = blockIdx.y;
    const int b  = blockIdx.z;
    const int tid = threadIdx.x;

#pragma unroll
    for (int it = 0; it < 4; it++) {
        int tr = it * 16 + (tid >> 4);
        int c4 = (tid & 15) * 4;
        float4 val = *(const float4*)&v[(size_t)(b * T_ + t0 + tr) * rowstride
                                        + g * HD_ + c4];
        s[tr][c4 + 0] = val.x; s[tr][c4 + 1] = val.y;
        s[tr][c4 + 2] = val.z; s[tr][c4 + 3] = val.w;
    }
    __syncthreads();

    const int hd  = tid >> 2;
    const int seg = tid & 3;
    __half hv[16];
#pragma unroll
    for (int j = 0; j < 16; j++)
        hv[j] = __float2half(s[seg * 16 + j][hd]);
    const size_t ob = ((size_t)(b * G_ + g) * HD_ + hd) * T_ + t0 + seg * 16;
    *(uint4*)&vt[ob]     = *(uint4*)&hv[0];
    *(uint4*)&vt[ob + 8] = *(uint4*)&hv[8];
}

// ---------------------------------------------------------------------------
// Causal GQA flash attention, HMMA fp16 single-pass.
// CTA = 256 q-rows, 8 warps (32 rows each), 64-key tiles,
// cp.async double-buffered K/V, 1 CTA/SM (8 warps).
// ---------------------------------------------------------------------------
#define ASTR  72
#define ATILE (64 * ASTR * 2)            // 9216 B
#define AQT   (256 * ASTR * 2)           // 36864 B
#define KVSTG (2 * ATILE)                // 18432 B per stage (K, V)
#define ATT_SMEM (AQT + 2 * KVSTG)       // 73728 B
#define SC_LOG2E 0.18033688011112042f

__global__ void __launch_bounds__(256, 1)
attn_mma(const __half* __restrict__ q16, const __half* __restrict__ k16,
         const __half* __restrict__ vt16, __half* __restrict__ o16)
{
    extern __shared__ char smraw[];
    const uint32_t sb  = smem_u32(smraw);
    const uint32_t sQ  = sb;
    const uint32_t sKV = sb + AQT;

    const int tid  = threadIdx.x;
    const int lane = tid & 31;
    const int w    = tid >> 5;            // 0..7
    const int mblk = gridDim.x - 1 - blockIdx.x;
    const int m0   = mblk * 256;
    const int h    = blockIdx.y;
    const int b    = blockIdx.z;
    const int g    = h >> 2;

    const __half* khb = k16 + ((size_t)b * T_ * G_ + g) * HD_;
    const __half* vhb = vt16 + (size_t)(b * G_ + g) * HD_ * T_;

    const int ntiles = (m0 + 256) / 64;

    const int ar = tid >> 3;             // 0..31
    const int ac = (tid & 7) * 8;
#define AISSUE(n0_, stg_) do {                                               \
        const uint32_t st_ = sKV + (uint32_t)(stg_) * KVSTG;                 \
        _Pragma("unroll")                                                    \
        for (int it_ = 0; it_ < 2; it_++) {                                  \
            const int rr_ = it_ * 32 + ar;                                   \
            const uint32_t so_ = (uint32_t)(rr_ * ASTR + ac) * 2;            \
            CP_ASYNC16(st_ + so_,         khb + (size_t)((n0_) + rr_) * (G_ * HD_) + ac); \
            CP_ASYNC16(st_ + ATILE + so_, vhb + (size_t)rr_ * T_ + (n0_) + ac); \
        }                                                                    \
        CP_COMMIT();                                                         \
    } while (0)

    AISSUE(0, 0);

    // ---- stage Q tile (256 rows) ----
    {
        const __half* qp = q16 + ((size_t)(b * T_ + m0) * H_ + h) * HD_;
        const uint32_t soff = (uint32_t)(ar * ASTR + ac) * 2;
#pragma unroll
        for (int it = 0; it < 8; it++) {
            uint4 a = *(const uint4*)(qp + (size_t)(it * 32 + ar) * (H_ * HD_) + ac);
            STS128(sQ + it * 32 * ASTR * 2 + soff, a);
        }
    }
    __syncthreads();

    uint32_t qf[2][4][4];
#pragma unroll
    for (int mt = 0; mt < 2; mt++) {
        const uint32_t a_off = (uint32_t)((w * 32 + mt * 16 + (lane & 15)) * ASTR * 2
                                          + (lane >> 4) * 16);
#pragma unroll
        for (int ks = 0; ks < 4; ks++)
            ldsm_x4(qf[mt][ks], sQ + a_off + ks * 32);
    }

    float o[2][8][4];
#pragma unroll
    for (int mt = 0; mt < 2; mt++)
#pragma unroll
        for (int nt = 0; nt < 8; nt++)
#pragma unroll
            for (int e = 0; e < 4; e++) o[mt][nt][e] = 0.f;
    float mrow[2][2] = {{-INFINITY, -INFINITY}, {-INFINITY, -INFINITY}};
    float lrow[2][2] = {{0.f, 0.f}, {0.f, 0.f}};

    const uint32_t b4_off = (uint32_t)((((lane & 7) + ((lane >> 4) & 1) * 8) * ASTR) * 2
                                       + ((lane >> 3) & 1) * 16);

    for (int t = 0; t < ntiles; t++) {
        CP_WAIT0();
        __syncthreads();
        if (t + 1 < ntiles) AISSUE((t + 1) * 64, (t + 1) & 1);

        const int n0 = t * 64;
        const uint32_t kvb = sKV + (uint32_t)(t & 1) * KVSTG;
        const uint32_t sK  = kvb;
        const uint32_t sV  = kvb + ATILE;

        const bool skip = (n0 > m0 + w * 32 + 31);
        if (!skip) {
            const bool needm = (n0 + 63 > m0 + w * 32);

            // ---- S = Q16 K16^T ----
            float s[2][8][4];
#pragma unroll
            for (int mt = 0; mt < 2; mt++)
#pragma unroll
                for (int nt = 0; nt < 8; nt++)
#pragma unroll
                    for (int e = 0; e < 4; e++) s[mt][nt][e] = 0.f;

#pragma unroll
            for (int ks = 0; ks < 4; ks++) {
#pragma unroll
                for (int ntp = 0; ntp < 4; ntp++) {
                    const uint32_t bo = b4_off + ntp * (16 * ASTR * 2) + ks * 32;
                    uint32_t bh[4];
                    ldsm_x4(bh, sK + bo);
#pragma unroll
                    for (int mt = 0; mt < 2; mt++) {
                        mma_f16(s[mt][2 * ntp],     qf[mt][ks], bh[0], bh[1]);
                        mma_f16(s[mt][2 * ntp + 1], qf[mt][ks], bh[2], bh[3]);
                    }
                }
            }

            // ---- per-group softmax; s dies into fp16 P fragments ----
            uint32_t ap[2][4][4];
#pragma unroll
            for (int mt = 0; mt < 2; mt++) {
                const int grow0 = m0 + w * 32 + mt * 16 + (lane >> 2);
                const int grow1 = grow0 + 8;
                float mx0 = -INFINITY, mx1 = -INFINITY;
#pragma unroll
                for (int nt = 0; nt < 8; nt++) {
                    const int col = n0 + nt * 8 + (lane & 3) * 2;
#pragma unroll
                    for (int e = 0; e < 2; e++) {
                        float v = s[mt][nt][e] * SC_LOG2E;
                        if (needm && (col + e > grow0)) v = -1e30f;
                        s[mt][nt][e] = v;
                        mx0 = fmaxf(mx0, v);
                    }
#pragma unroll
                    for (int e = 2; e < 4; e++) {
                        float v = s[mt][nt][e] * SC_LOG2E;
                        if (needm && (col + e - 2 > grow1)) v = -1e30f;
                        s[mt][nt][e] = v;
                        mx1 = fmaxf(mx1, v);
                    }
                }
                mx0 = fmaxf(mx0, __shfl_xor_sync(0xffffffffu, mx0, 1));
                mx0 = fmaxf(mx0, __shfl_xor_sync(0xffffffffu, mx0, 2));
                mx1 = fmaxf(mx1, __shfl_xor_sync(0xffffffffu, mx1, 1));
                mx1 = fmaxf(mx1, __shfl_xor_sync(0xffffffffu, mx1, 2));

                const float mn0 = fmaxf(mrow[mt][0], mx0);
                const float mn1 = fmaxf(mrow[mt][1], mx1);
                const float c0 = ex2(mrow[mt][0] - mn0);
                const float c1 = ex2(mrow[mt][1] - mn1);
                mrow[mt][0] = mn0; mrow[mt][1] = mn1;

                float s0 = 0.f, s1 = 0.f;
#pragma unroll
                for (int nt = 0; nt < 8; nt++) {
                    float p0 = ex2(s[mt][nt][0] - mn0);
                    float p1 = ex2(s[mt][nt][1] - mn0);
                    float p2 = ex2(s[mt][nt][2] - mn1);
                    float p3 = ex2(s[mt][nt][3] - mn1);
                    s[mt][nt][0] = p0; s[mt][nt][1] = p1;
                    s[mt][nt][2] = p2; s[mt][nt][3] = p3;
                    s0 += p0 + p1; s1 += p2 + p3;
                }
                s0 += __shfl_xor_sync(0xffffffffu, s0, 1);
                s0 += __shfl_xor_sync(0xffffffffu, s0, 2);
                s1 += __shfl_xor_sync(0xffffffffu, s1, 1);
                s1 += __shfl_xor_sync(0xffffffffu, s1, 2);
                lrow[mt][0] = lrow[mt][0] * c0 + s0;
                lrow[mt][1] = lrow[mt][1] * c1 + s1;

#pragma unroll
                for (int nt = 0; nt < 8; nt++) {
                    o[mt][nt][0] *= c0; o[mt][nt][1] *= c0;
                    o[mt][nt][2] *= c1; o[mt][nt][3] *= c1;
                }
#pragma unroll
                for (int ks = 0; ks < 4; ks++) {
                    ap[mt][ks][0] = pack_h2(s[mt][2 * ks][0],     s[mt][2 * ks][1]);
                    ap[mt][ks][1] = pack_h2(s[mt][2 * ks][2],     s[mt][2 * ks][3]);
                    ap[mt][ks][2] = pack_h2(s[mt][2 * ks + 1][0], s[mt][2 * ks + 1][1]);
                    ap[mt][ks][3] = pack_h2(s[mt][2 * ks + 1][2], s[mt][2 * ks + 1][3]);
                }
            }

            // ---- O += P16 V16 ----
#pragma unroll
            for (int ntp = 0; ntp < 4; ntp++) {
#pragma unroll
                for (int ks = 0; ks < 4; ks++) {
                    const uint32_t bo = b4_off + ntp * (16 * ASTR * 2) + ks * 32;
                    uint32_t vh[4];
                    ldsm_x4(vh, sV + bo);
#pragma unroll
                    for (int mt = 0; mt < 2; mt++) {
                        mma_f16(o[mt][2 * ntp],     ap[mt][ks], vh[0], vh[1]);
                        mma_f16(o[mt][2 * ntp + 1], ap[mt][ks], vh[2], vh[3]);
                    }
                }
            }
        }
    }
#undef AISSUE

    // ---- epilogue: normalize, emit single fp16 ----
#pragma unroll
    for (int mt = 0; mt < 2; mt++) {
        const float i0 = 1.f / lrow[mt][0];
        const float i1 = 1.f / lrow[mt][1];
        const int grow = m0 + w * 32 + mt * 16 + (lane >> 2);
        const size_t base0 = (size_t)(b * T_ + grow) * D_ + h * HD_ + (lane & 3) * 2;
        const size_t base1 = base0 + 8 * D_;
#pragma unroll
        for (int nt = 0; nt < 8; nt++) {
            *(uint32_t*)&o16[base0 + nt * 8] =
                pack_h2(o[mt][nt][0] * i0, o[mt][nt][1] * i0);
            *(uint32_t*)&o16[base1 + nt * 8] =
                pack_h2(o[mt][nt][2] * i1, o[mt][nt][3] * i1);
        }
    }
}

// ---------------------------------------------------------------------------
// Launch
// ---------------------------------------------------------------------------
extern "C" void kernel_launch(void* const* d_in, const int* in_sizes, int n_in,
                              void* d_out, int out_size)
{
    const float* x    = (const float*)d_in[0];
    const float* Wq   = (const float*)d_in[1];
    const float* Wk   = (const float*)d_in[2];
    const float* Wv   = (const float*)d_in[3];
    const float* Wo   = (const float*)d_in[4];
    const float* qn_w = (const float*)d_in[5];
    const float* kn_w = (const float*)d_in[6];
    float* out = (float*)d_out;

    float* qkvp;
    float2* cs;
    __half *x16, *wqkv16, *wo16, *q16, *k16, *vt16, *o16;
    cudaGetSymbolAddress((void**)&qkvp, g_qkv);
    cudaGetSymbolAddress((void**)&cs, g_cs);
    cudaGetSymbolAddress((void**)&x16, g_x16);
    cudaGetSymbolAddress((void**)&wqkv16, g_wqkv16);
    cudaGetSymbolAddress((void**)&wo16, g_wo16);
    cudaGetSymbolAddress((void**)&q16, g_q16);
    cudaGetSymbolAddress((void**)&k16, g_k16);
    cudaGetSymbolAddress((void**)&vt16, g_vt16);
    cudaGetSymbolAddress((void**)&o16, g_o16);

    cudaFuncSetAttribute(gemm_h1,
                         cudaFuncAttributeMaxDynamicSharedMemorySize, GEMM_SMEM);
    cudaFuncSetAttribute(attn_mma,
                         cudaFuncAttributeMaxDynamicSharedMemorySize, ATT_SMEM);

    // --- fused prologue ---
    prep<<<NB_TOT, 256>>>(x, Wq, Wk, Wv, Wo, x16, wqkv16, wo16, cs);

    // --- fused QKV projection (N = 1536) ---
    gemm_h1<<<dim3(QKVW / 128, BT_ / 128), 256, GEMM_SMEM>>>(
        x16, wqkv16, qkvp, BT_, QKVW, D_);

    // --- fused RMSNorm + RoPE (q + k); V convert+transpose ---
    rmsrope_qk<<<NB_RQ + NB_RK, 256>>>(qkvp, qn_w, kn_w, q16, k16, cs);
    vconv<<<dim3(T_ / 64, G_, B_), 256>>>(qkvp + D_ + 256, QKVW, vt16);

    // --- causal GQA flash attention (256 q-rows per CTA) ---
    attn_mma<<<dim3(T_ / 256, H_, B_), 256, ATT_SMEM>>>(q16, k16, vt16, o16);

    // --- output projection ---
    gemm_h1<<<dim3(D_ / 128, BT_ / 128), 256, GEMM_SMEM>>>(
        o16, wo16, out, BT_, D_, D_);
}

// round 13
// speedup vs baseline: 1.0279x; 1.0279x over previous
#include <cuda_runtime.h>
#include <cuda_fp16.h>
#include <math.h>
#include <stdint.h>

// ---------------------------------------------------------------------------
// Problem constants
// ---------------------------------------------------------------------------
#define B_   4
#define T_   2048
#define D_   1024
#define H_   16
#define G_   4
#define HD_  64
#define BT_  (B_ * T_)          // 8192
#define QKVW 1536                // fused Q|K|V projection width

// ---------------------------------------------------------------------------
// Scratch (device globals -- no allocation allowed)
// ---------------------------------------------------------------------------
__device__ float2 g_cs[T_ * 32];

__device__ __half g_qkv16[BT_ * QKVW];    // fused q|k|v projection (fp16)
__device__ __half g_x16[BT_ * D_];
__device__ __half g_wqkv16[QKVW * D_];    // Wq | Wk | Wv rows
__device__ __half g_wo16[D_ * D_];
__device__ __half g_q16[BT_ * D_];
__device__ __half g_k16[BT_ * G_ * HD_];
__device__ __half g_vt16[B_ * G_ * HD_ * T_];
__device__ __half g_o16[BT_ * D_];

// ---------------------------------------------------------------------------
// PTX helpers (base sm_100-legal)
// ---------------------------------------------------------------------------
__device__ __forceinline__ uint32_t smem_u32(const void* p) {
    uint32_t a;
    asm("{ .reg .u64 t; cvta.to.shared.u64 t, %1; cvt.u32.u64 %0, t; }"
        : "=r"(a) : "l"(p));
    return a;
}
__device__ __forceinline__ void ldsm_x4(uint32_t (&r)[4], uint32_t addr) {
    asm volatile("ldmatrix.sync.aligned.m8n8.x4.shared.b16 {%0,%1,%2,%3}, [%4];"
                 : "=r"(r[0]), "=r"(r[1]), "=r"(r[2]), "=r"(r[3]) : "r"(addr));
}
__device__ __forceinline__ void mma_f16(float (&d)[4], const uint32_t (&a)[4],
                                        uint32_t b0, uint32_t b1) {
    asm volatile(
        "mma.sync.aligned.m16n8k16.row.col.f32.f16.f16.f32 "
        "{%0,%1,%2,%3}, {%4,%5,%6,%7}, {%8,%9}, {%0,%1,%2,%3};"
        : "+f"(d[0]), "+f"(d[1]), "+f"(d[2]), "+f"(d[3])
        : "r"(a[0]), "r"(a[1]), "r"(a[2]), "r"(a[3]), "r"(b0), "r"(b1));
}
__device__ __forceinline__ float ex2(float x) {
    float y;
    asm("ex2.approx.ftz.f32 %0, %1;" : "=f"(y) : "f"(x));
    return y;
}
__device__ __forceinline__ uint32_t pack_h2(float x, float y) {
    __half2 h = __floats2half2_rn(x, y);
    return *(uint32_t*)&h;
}
#define STS128(addr, v) \
    asm volatile("st.shared.v4.b32 [%0], {%1,%2,%3,%4};" \
                 :: "r"(addr), "r"((v).x), "r"((v).y), "r"((v).z), "r"((v).w))
#define CP_ASYNC16(dst, src) \
    asm volatile("cp.async.cg.shared.global [%0], [%1], 16;" \
                 :: "r"(dst), "l"(src))
#define CP_COMMIT() asm volatile("cp.async.commit_group;" ::: "memory")
#define CP_WAIT1()  asm volatile("cp.async.wait_group 1;" ::: "memory")
#define CP_WAIT0()  asm volatile("cp.async.wait_group 0;" ::: "memory")

// ---------------------------------------------------------------------------
// Fused prologue: x->fp16, Wq|Wk|Wv|Wo->fp16, rope table. One launch.
// ---------------------------------------------------------------------------
#define NB_X   8192
#define NB_WQ  1024
#define NB_WK  256
#define NB_WV  256
#define NB_WO  1024
#define NB_CS  256
#define NB_TOT (NB_X + NB_WQ + NB_WK + NB_WV + NB_WO + NB_CS)

__global__ void __launch_bounds__(256)
prep(const float* __restrict__ x,  const float* __restrict__ Wq,
     const float* __restrict__ Wk, const float* __restrict__ Wv,
     const float* __restrict__ Wo,
     __half* __restrict__ x16, __half* __restrict__ wqkv16,
     __half* __restrict__ wo16, float2* __restrict__ cs)
{
    const int bid = blockIdx.x;
    const int tid = threadIdx.x;

    const float* src; __half* dst; int i;
    if (bid < NB_X) {
        i = bid * 256 + tid; src = x; dst = x16;
    } else if (bid < NB_X + NB_WQ) {
        i = (bid - NB_X) * 256 + tid; src = Wq; dst = wqkv16;
    } else if (bid < NB_X + NB_WQ + NB_WK) {
        i = (bid - NB_X - NB_WQ) * 256 + tid;
        src = Wk; dst = wqkv16 + (size_t)D_ * D_;
    } else if (bid < NB_X + NB_WQ + NB_WK + NB_WV) {
        i = (bid - NB_X - NB_WQ - NB_WK) * 256 + tid;
        src = Wv; dst = wqkv16 + (size_t)(D_ + 256) * D_;
    } else if (bid < NB_X + NB_WQ + NB_WK + NB_WV + NB_WO) {
        i = (bid - NB_X - NB_WQ - NB_WK - NB_WV) * 256 + tid;
        src = Wo; dst = wo16;
    } else {
        const int idx = (bid - (NB_TOT - NB_CS)) * 256 + tid;
        const int t = idx >> 5, l = idx & 31;
        double inv_freq = pow(10000.0, -(double)l / 32.0);
        double ang = (double)t * inv_freq;
        cs[idx] = make_float2((float)cos(ang), (float)sin(ang));
        return;
    }
    float4 v = ((const float4*)src)[i];
    uint2 o = {pack_h2(v.x, v.y), pack_h2(v.z, v.w)};
    ((uint2*)dst)[i] = o;
}

// ---------------------------------------------------------------------------
// Tensor-core GEMM (HMMA fp16): C[M,N] = A16[M,K] @ B16[N,K]^T.
// CTA 128x128, 8 warps, warp tile 64x32, KC=32, 3-stage cp.async, 2 CTAs/SM.
// HOUT: fp16 output (qkv) vs fp32 output (final).
// ---------------------------------------------------------------------------
#define KC      32
#define LDT     40
#define ATILEB  (128 * LDT * 2)
#define BTILEB  (128 * LDT * 2)
#define STAGEB  (ATILEB + BTILEB)
#define GEMM_SMEM (3 * STAGEB)            // 61440 B

template <bool HOUT>
__global__ void __launch_bounds__(256, 2)
gemm_h1(const __half* __restrict__ A16, const __half* __restrict__ B16,
        void* __restrict__ Cv, int M, int N, int K)
{
    extern __shared__ char smraw[];
    const uint32_t sb = smem_u32(smraw);

    const int tid  = threadIdx.x;
    const int lane = tid & 31;
    const int wid  = tid >> 5;
    const int wm   = wid & 1;
    const int wn   = wid >> 1;
    const int m0 = blockIdx.y * 128;
    const int n0 = blockIdx.x * 128;

    const int r0   = tid >> 2;
    const int cseg = (tid & 3) * 8;
    const __half* pA = A16 + (size_t)(m0 + r0) * K + cseg;
    const __half* pB = B16 + (size_t)(n0 + r0) * K + cseg;
    const uint32_t dA = (uint32_t)(r0 * LDT + cseg) * 2;
    const size_t rstep = (size_t)64 * K;
    const uint32_t dstep = 64 * LDT * 2;

    const uint32_t a_off = (uint32_t)(((wm * 64 + (lane & 15)) * LDT
                                       + (lane >> 4) * 8) * 2);
    const uint32_t b4_off = (uint32_t)(((wn * 32 + (lane & 7)
                                         + ((lane >> 4) & 1) * 8) * LDT) * 2
                                       + ((lane >> 3) & 1) * 16);

    float acc[4][4][4];
#pragma unroll
    for (int i = 0; i < 4; i++)
#pragma unroll
        for (int j = 0; j < 4; j++)
#pragma unroll
            for (int e = 0; e < 4; e++) acc[i][j][e] = 0.f;

    const int nch = K / KC;

#define ISSUE(c) do {                                                       \
        const uint32_t st_ = sb + ((c) % 3) * STAGEB;                       \
        const size_t k0_ = (size_t)(c) * KC;                                \
        CP_ASYNC16(st_ + dA,                    pA + k0_);                  \
        CP_ASYNC16(st_ + dA + dstep,            pA + k0_ + rstep);          \
        CP_ASYNC16(st_ + ATILEB + dA,           pB + k0_);                  \
        CP_ASYNC16(st_ + ATILEB + dA + dstep,   pB + k0_ + rstep);          \
        CP_COMMIT();                                                        \
    } while (0)

    ISSUE(0);
    ISSUE(1);

    for (int c = 0; c < nch; c++) {
        if (c + 2 < nch) CP_WAIT1(); else CP_WAIT0();
        __syncthreads();
        if (c + 2 < nch) ISSUE(c + 2);

        const uint32_t tb = sb + (c % 3) * STAGEB;
        const uint32_t aT = tb;
        const uint32_t bT = tb + ATILEB;

#pragma unroll
        for (int ks = 0; ks < 2; ks++) {
            const uint32_t ksb = ks * 32;
            uint32_t af[4][4];
#pragma unroll
            for (int mt = 0; mt < 4; mt++)
                ldsm_x4(af[mt], aT + a_off + mt * (16 * LDT * 2) + ksb);
#pragma unroll
            for (int ntp = 0; ntp < 2; ntp++) {
                uint32_t bh[4];
                ldsm_x4(bh, bT + b4_off + ntp * (16 * LDT * 2) + ksb);
#pragma unroll
                for (int mt = 0; mt < 4; mt++) {
                    mma_f16(acc[mt][2 * ntp],     af[mt], bh[0], bh[1]);
                    mma_f16(acc[mt][2 * ntp + 1], af[mt], bh[2], bh[3]);
                }
            }
        }
    }
#undef ISSUE

#pragma unroll
    for (int mt = 0; mt < 4; mt++) {
        const int r = m0 + wm * 64 + mt * 16 + (lane >> 2);
#pragma unroll
        for (int nt = 0; nt < 4; nt++) {
            const int cc = n0 + wn * 32 + nt * 8 + (lane & 3) * 2;
            if (HOUT) {
                __half* C = (__half*)Cv;
                *(uint32_t*)&C[(size_t)r * N + cc] =
                    pack_h2(acc[mt][nt][0], acc[mt][nt][1]);
                *(uint32_t*)&C[(size_t)(r + 8) * N + cc] =
                    pack_h2(acc[mt][nt][2], acc[mt][nt][3]);
            } else {
                float* C = (float*)Cv;
                float2 v0 = {acc[mt][nt][0], acc[mt][nt][1]};
                float2 v1 = {acc[mt][nt][2], acc[mt][nt][3]};
                *(float2*)&C[(size_t)r * N + cc]       = v0;
                *(float2*)&C[(size_t)(r + 8) * N + cc] = v1;
            }
        }
    }
}

// ---------------------------------------------------------------------------
// Fused RMSNorm + RoPE for q AND k, fp16 in (strided qkv) -> fp16 out.
// ---------------------------------------------------------------------------
#define NB_RQ (BT_ * H_ / 8)   // 16384
#define NB_RK (BT_ * G_ / 8)   // 4096

__global__ void __launch_bounds__(256)
rmsrope_qk(const __half* __restrict__ qkv,
           const float* __restrict__ qn_w, const float* __restrict__ kn_w,
           __half* __restrict__ q16, __half* __restrict__ k16,
           const float2* __restrict__ cs)
{
    const int lane   = threadIdx.x & 31;
    const int warpid = threadIdx.x >> 5;

    const __half* p;
    const float* w;
    __half* outp;
    int t;
    if (blockIdx.x < NB_RQ) {
        const int row  = blockIdx.x * 8 + warpid;
        const int bt   = row >> 4;
        const int head = row & 15;
        t = bt & (T_ - 1);
        p = qkv + (size_t)bt * QKVW + head * HD_;
        w = qn_w;
        outp = q16 + (size_t)bt * D_ + head * HD_;
    } else {
        const int row = (blockIdx.x - NB_RQ) * 8 + warpid;
        const int bt  = row >> 2;
        const int g   = row & 3;
        t = bt & (T_ - 1);
        p = qkv + (size_t)bt * QKVW + D_ + g * HD_;
        w = kn_w;
        outp = k16 + (size_t)bt * (G_ * HD_) + g * HD_;
    }

    __half2 xh = *(const __half2*)&p[2 * lane];
    float x0 = __half2float(__low2half(xh));
    float x1 = __half2float(__high2half(xh));

    float ss = x0 * x0 + x1 * x1;
#pragma unroll
    for (int o = 16; o > 0; o >>= 1)
        ss += __shfl_xor_sync(0xffffffffu, ss, o);

    float rms = rsqrtf(ss * (1.0f / HD_) + 1e-6f);
    float xn1 = x0 * rms * w[2 * lane];
    float xn2 = x1 * rms * w[2 * lane + 1];

    float2 csv = cs[t * 32 + lane];
    float ox = xn1 * csv.x - xn2 * csv.y;
    float oy = xn2 * csv.x + xn1 * csv.y;

    *(uint32_t*)&outp[2 * lane] = pack_h2(ox, oy);
}

// ---------------------------------------------------------------------------
// V transpose: fp16 strided [bt, 1536]+1280 -> fp16 [b,g,hd,T]
// ---------------------------------------------------------------------------
__global__ void __launch_bounds__(256)
vconv(const __half* __restrict__ v, int rowstride, __half* __restrict__ vt)
{
    __shared__ __half s[64][72];
    const int t0 = blockIdx.x * 64;
    const int g  = blockIdx.y;
    const int b  = blockIdx.z;
    const int tid = threadIdx.x;

#pragma unroll
    for (int it = 0; it < 2; it++) {
        int tr = it * 32 + (tid >> 3);
        int c8 = (tid & 7) * 8;
        uint4 raw = *(const uint4*)&v[(size_t)(b * T_ + t0 + tr) * rowstride
                                      + g * HD_ + c8];
        *(uint4*)&s[tr][c8] = raw;
    }
    __syncthreads();

    const int hd  = tid >> 2;
    const int seg = tid & 3;
    __half hv[16];
#pragma unroll
    for (int j = 0; j < 16; j++)
        hv[j] = s[seg * 16 + j][hd];
    const size_t ob = ((size_t)(b * G_ + g) * HD_ + hd) * T_ + t0 + seg * 16;
    *(uint4*)&vt[ob]     = *(uint4*)&hv[0];
    *(uint4*)&vt[ob + 8] = *(uint4*)&hv[8];
}

// ---------------------------------------------------------------------------
// Causal GQA flash attention, HMMA fp16 single-pass (round-11 proven config).
// CTA = 128 q-rows, 4 warps (32 rows each), 64-key tiles,
// cp.async double-buffered K/V, 2 CTAs/SM.
// ---------------------------------------------------------------------------
#define ASTR  72
#define ATILE (64 * ASTR * 2)            // 9216 B
#define AQT   (128 * ASTR * 2)           // 18432 B
#define KVSTG (2 * ATILE)                // 18432 B per stage (K, V)
#define ATT_SMEM (AQT + 2 * KVSTG)       // 55296 B
#define SC_LOG2E 0.18033688011112042f

__global__ void __launch_bounds__(128)
attn_mma(const __half* __restrict__ q16, const __half* __restrict__ k16,
         const __half* __restrict__ vt16, __half* __restrict__ o16)
{
    extern __shared__ char smraw[];
    const uint32_t sb  = smem_u32(smraw);
    const uint32_t sQ  = sb;
    const uint32_t sKV = sb + AQT;

    const int tid  = threadIdx.x;
    const int lane = tid & 31;
    const int w    = tid >> 5;
    const int mblk = gridDim.x - 1 - blockIdx.x;
    const int m0   = mblk * 128;
    const int h    = blockIdx.y;
    const int b    = blockIdx.z;
    const int g    = h >> 2;

    const __half* khb = k16 + ((size_t)b * T_ * G_ + g) * HD_;
    const __half* vhb = vt16 + (size_t)(b * G_ + g) * HD_ * T_;

    const int ntiles = (m0 + 128) / 64;

    const int ar = tid >> 3;             // 0..15
    const int ac = (tid & 7) * 8;
#define AISSUE(n0_, stg_) do {                                               \
        const uint32_t st_ = sKV + (uint32_t)(stg_) * KVSTG;                 \
        _Pragma("unroll")                                                    \
        for (int it_ = 0; it_ < 4; it_++) {                                  \
            const int rr_ = it_ * 16 + ar;                                   \
            const uint32_t so_ = (uint32_t)(rr_ * ASTR + ac) * 2;            \
            CP_ASYNC16(st_ + so_,         khb + (size_t)((n0_) + rr_) * (G_ * HD_) + ac); \
            CP_ASYNC16(st_ + ATILE + so_, vhb + (size_t)rr_ * T_ + (n0_) + ac); \
        }                                                                    \
        CP_COMMIT();                                                         \
    } while (0)

    AISSUE(0, 0);

    {
        const __half* qp = q16 + ((size_t)(b * T_ + m0) * H_ + h) * HD_;
        const uint32_t soff = (uint32_t)(ar * ASTR + ac) * 2;
#pragma unroll
        for (int it = 0; it < 8; it++) {
            uint4 a = *(const uint4*)(qp + (size_t)(it * 16 + ar) * (H_ * HD_) + ac);
            STS128(sQ + it * 16 * ASTR * 2 + soff, a);
        }
    }
    __syncthreads();

    uint32_t qf[2][4][4];
#pragma unroll
    for (int mt = 0; mt < 2; mt++) {
        const uint32_t a_off = (uint32_t)((w * 32 + mt * 16 + (lane & 15)) * ASTR * 2
                                          + (lane >> 4) * 16);
#pragma unroll
        for (int ks = 0; ks < 4; ks++)
            ldsm_x4(qf[mt][ks], sQ + a_off + ks * 32);
    }

    float o[2][8][4];
#pragma unroll
    for (int mt = 0; mt < 2; mt++)
#pragma unroll
        for (int nt = 0; nt < 8; nt++)
#pragma unroll
            for (int e = 0; e < 4; e++) o[mt][nt][e] = 0.f;
    float mrow[2][2] = {{-INFINITY, -INFINITY}, {-INFINITY, -INFINITY}};
    float lrow[2][2] = {{0.f, 0.f}, {0.f, 0.f}};

    const uint32_t b4_off = (uint32_t)((((lane & 7) + ((lane >> 4) & 1) * 8) * ASTR) * 2
                                       + ((lane >> 3) & 1) * 16);

    for (int t = 0; t < ntiles; t++) {
        CP_WAIT0();
        __syncthreads();
        if (t + 1 < ntiles) AISSUE((t + 1) * 64, (t + 1) & 1);

        const int n0 = t * 64;
        const uint32_t kvb = sKV + (uint32_t)(t & 1) * KVSTG;
        const uint32_t sK  = kvb;
        const uint32_t sV  = kvb + ATILE;

        const bool skip = (n0 > m0 + w * 32 + 31);
        if (!skip) {
            const bool needm = (n0 + 63 > m0 + w * 32);

            float s[2][8][4];
#pragma unroll
            for (int mt = 0; mt < 2; mt++)
#pragma unroll
                for (int nt = 0; nt < 8; nt++)
#pragma unroll
                    for (int e = 0; e < 4; e++) s[mt][nt][e] = 0.f;

#pragma unroll
            for (int ks = 0; ks < 4; ks++) {
#pragma unroll
                for (int ntp = 0; ntp < 4; ntp++) {
                    const uint32_t bo = b4_off + ntp * (16 * ASTR * 2) + ks * 32;
                    uint32_t bh[4];
                    ldsm_x4(bh, sK + bo);
#pragma unroll
                    for (int mt = 0; mt < 2; mt++) {
                        mma_f16(s[mt][2 * ntp],     qf[mt][ks], bh[0], bh[1]);
                        mma_f16(s[mt][2 * ntp + 1], qf[mt][ks], bh[2], bh[3]);
                    }
                }
            }

            uint32_t ap[2][4][4];
#pragma unroll
            for (int mt = 0; mt < 2; mt++) {
                const int grow0 = m0 + w * 32 + mt * 16 + (lane >> 2);
                const int grow1 = grow0 + 8;
                float mx0 = -INFINITY, mx1 = -INFINITY;
#pragma unroll
                for (int nt = 0; nt < 8; nt++) {
                    const int col = n0 + nt * 8 + (lane & 3) * 2;
#pragma unroll
                    for (int e = 0; e < 2; e++) {
                        float v = s[mt][nt][e] * SC_LOG2E;
                        if (needm && (col + e > grow0)) v = -1e30f;
                        s[mt][nt][e] = v;
                        mx0 = fmaxf(mx0, v);
                    }
#pragma unroll
                    for (int e = 2; e < 4; e++) {
                        float v = s[mt][nt][e] * SC_LOG2E;
                        if (needm && (col + e - 2 > grow1)) v = -1e30f;
                        s[mt][nt][e] = v;
                        mx1 = fmaxf(mx1, v);
                    }
                }
                mx0 = fmaxf(mx0, __shfl_xor_sync(0xffffffffu, mx0, 1));
                mx0 = fmaxf(mx0, __shfl_xor_sync(0xffffffffu, mx0, 2));
                mx1 = fmaxf(mx1, __shfl_xor_sync(0xffffffffu, mx1, 1));
                mx1 = fmaxf(mx1, __shfl_xor_sync(0xffffffffu, mx1, 2));

                const float mn0 = fmaxf(mrow[mt][0], mx0);
                const float mn1 = fmaxf(mrow[mt][1], mx1);
                const float c0 = ex2(mrow[mt][0] - mn0);
                const float c1 = ex2(mrow[mt][1] - mn1);
                mrow[mt][0] = mn0; mrow[mt][1] = mn1;

                float s0 = 0.f, s1 = 0.f;
#pragma unroll
                for (int nt = 0; nt < 8; nt++) {
                    float p0 = ex2(s[mt][nt][0] - mn0);
                    float p1 = ex2(s[mt][nt][1] - mn0);
                    float p2 = ex2(s[mt][nt][2] - mn1);
                    float p3 = ex2(s[mt][nt][3] - mn1);
                    s[mt][nt][0] = p0; s[mt][nt][1] = p1;
                    s[mt][nt][2] = p2; s[mt][nt][3] = p3;
                    s0 += p0 + p1; s1 += p2 + p3;
                }
                s0 += __shfl_xor_sync(0xffffffffu, s0, 1);
                s0 += __shfl_xor_sync(0xffffffffu, s0, 2);
                s1 += __shfl_xor_sync(0xffffffffu, s1, 1);
                s1 += __shfl_xor_sync(0xffffffffu, s1, 2);
                lrow[mt][0] = lrow[mt][0] * c0 + s0;
                lrow[mt][1] = lrow[mt][1] * c1 + s1;

#pragma unroll
                for (int nt = 0; nt < 8; nt++) {
                    o[mt][nt][0] *= c0; o[mt][nt][1] *= c0;
                    o[mt][nt][2] *= c1; o[mt][nt][3] *= c1;
                }
#pragma unroll
                for (int ks = 0; ks < 4; ks++) {
                    ap[mt][ks][0] = pack_h2(s[mt][2 * ks][0],     s[mt][2 * ks][1]);
                    ap[mt][ks][1] = pack_h2(s[mt][2 * ks][2],     s[mt][2 * ks][3]);
                    ap[mt][ks][2] = pack_h2(s[mt][2 * ks + 1][0], s[mt][2 * ks + 1][1]);
                    ap[mt][ks][3] = pack_h2(s[mt][2 * ks + 1][2], s[mt][2 * ks + 1][3]);
                }
            }

#pragma unroll
            for (int ntp = 0; ntp < 4; ntp++) {
#pragma unroll
                for (int ks = 0; ks < 4; ks++) {
                    const uint32_t bo = b4_off + ntp * (16 * ASTR * 2) + ks * 32;
                    uint32_t vh[4];
                    ldsm_x4(vh, sV + bo);
#pragma unroll
                    for (int mt = 0; mt < 2; mt++) {
                        mma_f16(o[mt][2 * ntp],     ap[mt][ks], vh[0], vh[1]);
                        mma_f16(o[mt][2 * ntp + 1], ap[mt][ks], vh[2], vh[3]);
                    }
                }
            }
        }
    }
#undef AISSUE

#pragma unroll
    for (int mt = 0; mt < 2; mt++) {
        const float i0 = 1.f / lrow[mt][0];
        const float i1 = 1.f / lrow[mt][1];
        const int grow = m0 + w * 32 + mt * 16 + (lane >> 2);
        const size_t base0 = (size_t)(b * T_ + grow) * D_ + h * HD_ + (lane & 3) * 2;
        const size_t base1 = base0 + 8 * D_;
#pragma unroll
        for (int nt = 0; nt < 8; nt++) {
            *(uint32_t*)&o16[base0 + nt * 8] =
                pack_h2(o[mt][nt][0] * i0, o[mt][nt][1] * i0);
            *(uint32_t*)&o16[base1 + nt * 8] =
                pack_h2(o[mt][nt][2] * i1, o[mt][nt][3] * i1);
        }
    }
}

// ---------------------------------------------------------------------------
// Launch
// ---------------------------------------------------------------------------
extern "C" void kernel_launch(void* const* d_in, const int* in_sizes, int n_in,
                              void* d_out, int out_size)
{
    const float* x    = (const float*)d_in[0];
    const float* Wq   = (const float*)d_in[1];
    const float* Wk   = (const float*)d_in[2];
    const float* Wv   = (const float*)d_in[3];
    const float* Wo   = (const float*)d_in[4];
    const float* qn_w = (const float*)d_in[5];
    const float* kn_w = (const float*)d_in[6];
    float* out = (float*)d_out;

    float2* cs;
    __half *qkv16, *x16, *wqkv16, *wo16, *q16, *k16, *vt16, *o16;
    cudaGetSymbolAddress((void**)&cs, g_cs);
    cudaGetSymbolAddress((void**)&qkv16, g_qkv16);
    cudaGetSymbolAddress((void**)&x16, g_x16);
    cudaGetSymbolAddress((void**)&wqkv16, g_wqkv16);
    cudaGetSymbolAddress((void**)&wo16, g_wo16);
    cudaGetSymbolAddress((void**)&q16, g_q16);
    cudaGetSymbolAddress((void**)&k16, g_k16);
    cudaGetSymbolAddress((void**)&vt16, g_vt16);
    cudaGetSymbolAddress((void**)&o16, g_o16);

    cudaFuncSetAttribute(gemm_h1<true>,
                         cudaFuncAttributeMaxDynamicSharedMemorySize, GEMM_SMEM);
    cudaFuncSetAttribute(gemm_h1<false>,
                         cudaFuncAttributeMaxDynamicSharedMemorySize, GEMM_SMEM);
    cudaFuncSetAttribute(attn_mma,
                         cudaFuncAttributeMaxDynamicSharedMemorySize, ATT_SMEM);

    // --- fused prologue ---
    prep<<<NB_TOT, 256>>>(x, Wq, Wk, Wv, Wo, x16, wqkv16, wo16, cs);

    // --- fused QKV projection (fp16 output) ---
    gemm_h1<true><<<dim3(QKVW / 128, BT_ / 128), 256, GEMM_SMEM>>>(
        x16, wqkv16, qkv16, BT_, QKVW, D_);

    // --- fused RMSNorm + RoPE (q + k); V transpose ---
    rmsrope_qk<<<NB_RQ + NB_RK, 256>>>(qkv16, qn_w, kn_w, q16, k16, cs);
    vconv<<<dim3(T_ / 64, G_, B_), 256>>>(qkv16 + D_ + 256, QKVW, vt16);

    // --- causal GQA flash attention (128 q-rows, 2 CTAs/SM) ---
    attn_mma<<<dim3(T_ / 128, H_, B_), 128, ATT_SMEM>>>(q16, k16, vt16, o16);

    // --- output projection (fp32 output) ---
    gemm_h1<false><<<dim3(D_ / 128, BT_ / 128), 256, GEMM_SMEM>>>(
        o16, wo16, out, BT_, D_, D_);
}